// round 1
// baseline (speedup 1.0000x reference)
#include <cuda_runtime.h>
#include <math.h>

#define BATCH   4
#define SEQ     2048
#define DMODEL  768
#define NHEADS  12
#define HDIM    64
#define MTOT    (BATCH*SEQ)   /* 8192 */

// Scratch (static device arrays: allocation-free per harness rules)
__device__ float g_Q [MTOT*DMODEL];
__device__ float g_K [MTOT*DMODEL];
__device__ float g_V [MTOT*DMODEL];
__device__ float g_AO[MTOT*DMODEL];

// ---------------------------------------------------------------------------
// C[M,N] = A[M,K] @ B[N,K]^T   (both operands K-contiguous row-major)
// 64x64 tile, 256 threads, 4x4 accumulators per thread, K-step 16.
// ---------------------------------------------------------------------------
__global__ __launch_bounds__(256) void gemm_abt_kernel(
    const float* __restrict__ A, const float* __restrict__ B,
    float* __restrict__ C, int M, int N, int K)
{
    __shared__ float As[16][64];
    __shared__ float Bs[16][64];

    const int tid = threadIdx.x;
    const int tx  = tid & 15;       // 0..15  (N direction)
    const int ty  = tid >> 4;       // 0..15  (M direction)
    const int m0  = blockIdx.y * 64;
    const int n0  = blockIdx.x * 64;
    const int lrow = tid >> 2;      // 0..63
    const int lc4  = tid & 3;       // 0..3

    float acc[4][4] = {};

    const float* aptr = A + (size_t)(m0 + lrow) * K + lc4 * 4;
    const float* bptr = B + (size_t)(n0 + lrow) * K + lc4 * 4;

    for (int k0 = 0; k0 < K; k0 += 16) {
        float4 av = *(const float4*)(aptr + k0);
        float4 bv = *(const float4*)(bptr + k0);
        As[lc4*4+0][lrow] = av.x; As[lc4*4+1][lrow] = av.y;
        As[lc4*4+2][lrow] = av.z; As[lc4*4+3][lrow] = av.w;
        Bs[lc4*4+0][lrow] = bv.x; Bs[lc4*4+1][lrow] = bv.y;
        Bs[lc4*4+2][lrow] = bv.z; Bs[lc4*4+3][lrow] = bv.w;
        __syncthreads();

        #pragma unroll
        for (int kk = 0; kk < 16; kk++) {
            float4 a = *(const float4*)&As[kk][ty*4];
            float4 b = *(const float4*)&Bs[kk][tx*4];
            acc[0][0] += a.x*b.x; acc[0][1] += a.x*b.y; acc[0][2] += a.x*b.z; acc[0][3] += a.x*b.w;
            acc[1][0] += a.y*b.x; acc[1][1] += a.y*b.y; acc[1][2] += a.y*b.z; acc[1][3] += a.y*b.w;
            acc[2][0] += a.z*b.x; acc[2][1] += a.z*b.y; acc[2][2] += a.z*b.z; acc[2][3] += a.z*b.w;
            acc[3][0] += a.w*b.x; acc[3][1] += a.w*b.y; acc[3][2] += a.w*b.z; acc[3][3] += a.w*b.w;
        }
        __syncthreads();
    }

    #pragma unroll
    for (int i = 0; i < 4; i++) {
        float4 r = make_float4(acc[i][0], acc[i][1], acc[i][2], acc[i][3]);
        *(float4*)&C[(size_t)(m0 + ty*4 + i) * N + n0 + tx*4] = r;
    }
}

// ---------------------------------------------------------------------------
// RoPE on Q and K, interleaved-pair convention, with the 1/sqrt(64)=0.125
// scale folded into Q (exact power-of-two multiply).
// Angle computed as fp32 (s * fp32(inv_freq)) to match the reference's fp32
// angle, then sin/cos evaluated in double (immune to fast-math __sinf).
// ---------------------------------------------------------------------------
__global__ void rope_kernel()
{
    int idx = blockIdx.x * blockDim.x + threadIdx.x;
    const int total = MTOT * NHEADS * (HDIM/2);
    if (idx >= total) return;

    int j  = idx & 31;                 // pair index within head (HDIM/2 = 32)
    int h  = (idx >> 5) % NHEADS;
    int ms = idx / (32 * NHEADS);      // b*SEQ + s
    int s  = ms & (SEQ - 1);

    float invf = (float)pow(10000.0, -(double)(2*j) / (double)HDIM);
    float angf = (float)s * invf;
    double sn_d, cs_d;
    sincos((double)angf, &sn_d, &cs_d);
    float sn = (float)sn_d, cs = (float)cs_d;

    int base = ms * DMODEL + h * HDIM + 2*j;
    float q1 = g_Q[base], q2 = g_Q[base+1];
    g_Q[base]   = (q1*cs - q2*sn) * 0.125f;
    g_Q[base+1] = (q1*sn + q2*cs) * 0.125f;
    float k1 = g_K[base], k2 = g_K[base+1];
    g_K[base]   = k1*cs - k2*sn;
    g_K[base+1] = k1*sn + k2*cs;
}

// ---------------------------------------------------------------------------
// Causal flash attention, fp32. One q row per thread (q + accumulator live
// in registers), K/V tiles (32 x 64) staged in shared and read as broadcast
// LDS.128. Scores staged in shared Sc[j][t] (bank-conflict-free; avoids
// local-memory spill from dynamically indexed register arrays).
// Grid: (SEQ/128, BATCH*NHEADS), 128 threads.
// ---------------------------------------------------------------------------
__global__ __launch_bounds__(128) void attn_kernel()
{
    __shared__ float Ks[32][64];
    __shared__ float Vs[32][64];
    __shared__ float Sc[32][128];

    const int t  = threadIdx.x;
    const int bh = blockIdx.y;
    const int b  = bh / NHEADS;
    const int h  = bh % NHEADS;
    const int q0 = blockIdx.x * 128;
    const int qrow = q0 + t;
    const size_t headbase = (size_t)(b * SEQ) * DMODEL + h * HDIM;

    float4 q[16];
    #pragma unroll
    for (int d = 0; d < 16; d++)
        q[d] = *(const float4*)&g_Q[headbase + (size_t)qrow * DMODEL + d*4];

    float4 o[16];
    #pragma unroll
    for (int d = 0; d < 16; d++) o[d] = make_float4(0.f, 0.f, 0.f, 0.f);

    float m = -INFINITY, l = 0.f;

    const int ktiles = (q0 + 128) >> 5;   // causal: only tiles with kb <= q0+127
    for (int kt = 0; kt < ktiles; kt++) {
        const int kb = kt << 5;

        #pragma unroll
        for (int i = 0; i < 4; i++) {
            int idx = t + i * 128;
            int r = idx >> 4, c = (idx & 15) * 4;
            *(float4*)&Ks[r][c] = *(const float4*)&g_K[headbase + (size_t)(kb + r) * DMODEL + c];
            *(float4*)&Vs[r][c] = *(const float4*)&g_V[headbase + (size_t)(kb + r) * DMODEL + c];
        }
        __syncthreads();

        float mt = m;
        #pragma unroll 4
        for (int j = 0; j < 32; j++) {
            float sx = 0.f, sy = 0.f, sz = 0.f, sw = 0.f;
            #pragma unroll
            for (int d = 0; d < 16; d++) {
                float4 kv = *(const float4*)&Ks[j][d*4];
                sx += q[d].x * kv.x;  sy += q[d].y * kv.y;
                sz += q[d].z * kv.z;  sw += q[d].w * kv.w;
            }
            float sc = (sx + sy) + (sz + sw);       // scale already folded into q
            sc = (kb + j <= qrow) ? sc : -1e30f;    // causal mask
            Sc[j][t] = sc;
            mt = fmaxf(mt, sc);
        }

        float corr = __expf(m - mt);
        m = mt;
        l *= corr;
        #pragma unroll
        for (int d = 0; d < 16; d++) {
            o[d].x *= corr; o[d].y *= corr; o[d].z *= corr; o[d].w *= corr;
        }

        #pragma unroll 4
        for (int j = 0; j < 32; j++) {
            float p = __expf(Sc[j][t] - m);
            l += p;
            #pragma unroll
            for (int d = 0; d < 16; d++) {
                float4 vv = *(const float4*)&Vs[j][d*4];
                o[d].x += p * vv.x; o[d].y += p * vv.y;
                o[d].z += p * vv.z; o[d].w += p * vv.w;
            }
        }
        __syncthreads();
    }

    const float invl = 1.f / l;
    #pragma unroll
    for (int d = 0; d < 16; d++) {
        float4 r = make_float4(o[d].x*invl, o[d].y*invl, o[d].z*invl, o[d].w*invl);
        *(float4*)&g_AO[headbase + (size_t)qrow * DMODEL + d*4] = r;
    }
}

// ---------------------------------------------------------------------------
extern "C" void kernel_launch(void* const* d_in, const int* in_sizes, int n_in,
                              void* d_out, int out_size)
{
    const float* x  = (const float*)d_in[0];
    const float* wq = (const float*)d_in[1];
    const float* wk = (const float*)d_in[2];
    const float* wv = (const float*)d_in[3];
    const float* wo = (const float*)d_in[4];
    float* out = (float*)d_out;

    float *Q, *K, *V, *AO;
    cudaGetSymbolAddress((void**)&Q,  g_Q);
    cudaGetSymbolAddress((void**)&K,  g_K);
    cudaGetSymbolAddress((void**)&V,  g_V);
    cudaGetSymbolAddress((void**)&AO, g_AO);

    dim3 gblk(256);
    dim3 ggrid(DMODEL/64, MTOT/64);   // (12, 128)

    gemm_abt_kernel<<<ggrid, gblk>>>(x, wq, Q, MTOT, DMODEL, DMODEL);
    gemm_abt_kernel<<<ggrid, gblk>>>(x, wk, K, MTOT, DMODEL, DMODEL);
    gemm_abt_kernel<<<ggrid, gblk>>>(x, wv, V, MTOT, DMODEL, DMODEL);

    const int rtotal = MTOT * NHEADS * (HDIM/2);
    rope_kernel<<<(rtotal + 255) / 256, 256>>>();

    attn_kernel<<<dim3(SEQ/128, BATCH*NHEADS), 128>>>();

    gemm_abt_kernel<<<ggrid, gblk>>>(AO, wo, out, MTOT, DMODEL, DMODEL);
}